// round 2
// baseline (speedup 1.0000x reference)
#include <cuda_runtime.h>
#include <math.h>

// Problem constants
#define BB    64
#define MAXT  511
#define TP1   512
#define SDIM  1024
#define HDIM  4096
#define W2S   32

// Tiling
#define MT       32          // rows (timesteps) per block
#define NT       256         // H columns per n-tile
#define KT       16          // k-chunk depth
#define NTILES   (HDIM/NT)   // 16
#define NCHUNK   (SDIM/KT)   // 64
#define THREADS  256
#define TILES_PER_B ((MAXT + MT - 1)/MT)   // 16
#define NBLK     (BB*TILES_PER_B)          // 1024

#define ST_PAD   36                         // padded row (floats), 16B aligned
#define SMEM_ST   (SDIM*ST_PAD)             // 36864 floats
#define SMEM_W    (2*KT*NT)                 // 8192 floats
#define SMEM_PART 256
#define SMEM_RED  32
#define SMEM_FLOATS (SMEM_ST + SMEM_W + SMEM_PART + SMEM_RED)
#define SMEM_BYTES  (SMEM_FLOATS*4)

typedef unsigned long long u64t;

__device__ float g_blocksums[NBLK];

__device__ __forceinline__ u64t pk2(float lo, float hi){
    u64t r; asm("mov.b64 %0, {%1,%2};" : "=l"(r) : "f"(lo), "f"(hi)); return r;
}
__device__ __forceinline__ void upk2(u64t v, float& lo, float& hi){
    asm("mov.b64 {%0,%1}, %2;" : "=f"(lo), "=f"(hi) : "l"(v));
}
__device__ __forceinline__ u64t ffma2(u64t a, u64t b, u64t c){
    u64t d; asm("fma.rn.f32x2 %0, %1, %2, %3;" : "=l"(d) : "l"(a), "l"(b), "l"(c)); return d;
}

extern "C" __global__ void __launch_bounds__(THREADS, 1)
traj_main(const float* __restrict__ s_in, const int* __restrict__ actions,
          const int* __restrict__ lengths, const float* __restrict__ W1,
          const float* __restrict__ b1, const float* __restrict__ W2,
          const float* __restrict__ b2)
{
    extern __shared__ float smem[];
    float* sT   = smem;                 // [1024][36] transposed s tile
    float* wb   = smem + SMEM_ST;       // [2][KT][NT] W1 double buffer
    float* part = wb + SMEM_W;          // [8 warps][32]
    float* red  = part + SMEM_PART;     // [32]

    const int tile   = blockIdx.x;
    const int b      = blockIdx.y;
    const int bid    = b * TILES_PER_B + tile;
    const int t_base = tile * MT;
    const int len    = lengths[b];
    const int tid    = threadIdx.x;

    if (t_base >= len) {                 // whole tile masked out
        if (tid == 0) g_blocksums[bid] = 0.f;
        return;
    }

    // ---- load s tile [32 rows x 1024] transposed into SMEM ----
    const float* srow = s_in + ((size_t)b * TP1 + t_base) * SDIM;
    #pragma unroll 4
    for (int it = 0; it < (MT*SDIM/4)/THREADS; ++it) {   // 32 iters
        int idx = it * THREADS + tid;
        int kq  = idx >> 5;        // float4 index along k (0..255)
        int m   = idx & 31;        // row
        float4 v = *(const float4*)(srow + (size_t)m * SDIM + kq * 4);
        int k = kq * 4;
        sT[(k+0)*ST_PAD + m] = v.x;
        sT[(k+1)*ST_PAD + m] = v.y;
        sT[(k+2)*ST_PAD + m] = v.z;
        sT[(k+3)*ST_PAD + m] = v.w;
    }
    __syncthreads();

    const int tx  = tid & 63;      // 64 col groups of 4
    const int ty  = tid >> 6;      // 4 row groups of 8
    const int tx4 = tx * 4;

    unsigned sT_u = (unsigned)__cvta_generic_to_shared(sT);
    unsigned aAddrBase = sT_u + (unsigned)(ty * 8) * 4u;

    // W1 staging indices: each thread moves 4 float4 per chunk
    int wk[4], wn[4];
    #pragma unroll
    for (int j = 0; j < 4; ++j) {
        int fidx = j * THREADS + tid;
        wk[j] = fidx >> 6;            // 0..15
        wn[j] = (fidx & 63) * 4;      // 0..252
    }

    float plog[8][4];                 // partial logits (8 rows x 4 actions)
    #pragma unroll
    for (int i = 0; i < 8; ++i)
        #pragma unroll
        for (int a = 0; a < 4; ++a) plog[i][a] = 0.f;

    for (int ntile = 0; ntile < NTILES; ++ntile) {
        const int n0 = ntile * NT;
        u64t c2[4][4];                // 4 row-pairs x 4 cols (f32x2)
        #pragma unroll
        for (int p = 0; p < 4; ++p)
            #pragma unroll
            for (int j = 0; j < 4; ++j) c2[p][j] = 0ull;

        // stage chunk 0
        #pragma unroll
        for (int j = 0; j < 4; ++j) {
            float4 v = *(const float4*)(W1 + (size_t)wk[j]*HDIM + n0 + wn[j]);
            *(float4*)&wb[wk[j]*NT + wn[j]] = v;
        }
        __syncthreads();

        int buf = 0;
        for (int ck = 0; ck < NCHUNK; ++ck) {
            float4 pre[4];
            if (ck + 1 < NCHUNK) {
                #pragma unroll
                for (int j = 0; j < 4; ++j)
                    pre[j] = *(const float4*)(W1 + (size_t)((ck+1)*KT + wk[j])*HDIM + n0 + wn[j]);
            }
            const float* wcur = wb + buf * (KT*NT);
            const int kbase = ck * KT;
            #pragma unroll
            for (int kk = 0; kk < KT; ++kk) {
                int kg = kbase + kk;
                u64t a2[4];
                unsigned aAddr = aAddrBase + (unsigned)(kg * ST_PAD) * 4u;
                asm volatile("ld.shared.v2.b64 {%0,%1}, [%2];"
                             : "=l"(a2[0]), "=l"(a2[1]) : "r"(aAddr));
                asm volatile("ld.shared.v2.b64 {%0,%1}, [%2];"
                             : "=l"(a2[2]), "=l"(a2[3]) : "r"(aAddr + 16u));
                float4 bv = *(const float4*)&wcur[kk*NT + tx4];
                u64t bs0 = pk2(bv.x, bv.x);
                u64t bs1 = pk2(bv.y, bv.y);
                u64t bs2 = pk2(bv.z, bv.z);
                u64t bs3 = pk2(bv.w, bv.w);
                #pragma unroll
                for (int p = 0; p < 4; ++p) {
                    c2[p][0] = ffma2(a2[p], bs0, c2[p][0]);
                    c2[p][1] = ffma2(a2[p], bs1, c2[p][1]);
                    c2[p][2] = ffma2(a2[p], bs2, c2[p][2]);
                    c2[p][3] = ffma2(a2[p], bs3, c2[p][3]);
                }
            }
            if (ck + 1 < NCHUNK) {
                float* wnxt = wb + (buf^1) * (KT*NT);
                #pragma unroll
                for (int j = 0; j < 4; ++j)
                    *(float4*)&wnxt[wk[j]*NT + wn[j]] = pre[j];
                __syncthreads();
                buf ^= 1;
            }
        }

        // fused stage-2: h = relu(c + b1), plog += h * W2[:,0:4]
        #pragma unroll
        for (int nj = 0; nj < 4; ++nj) {
            int n = n0 + tx4 + nj;
            float bias  = __ldg(b1 + n);
            float4 w2v  = *(const float4*)(W2 + (size_t)n * W2S);
            #pragma unroll
            for (int p = 0; p < 4; ++p) {
                float h0, h1; upk2(c2[p][nj], h0, h1);
                h0 = fmaxf(h0 + bias, 0.f);
                h1 = fmaxf(h1 + bias, 0.f);
                plog[2*p  ][0] += h0 * w2v.x;  plog[2*p  ][1] += h0 * w2v.y;
                plog[2*p  ][2] += h0 * w2v.z;  plog[2*p  ][3] += h0 * w2v.w;
                plog[2*p+1][0] += h1 * w2v.x;  plog[2*p+1][1] += h1 * w2v.y;
                plog[2*p+1][2] += h1 * w2v.z;  plog[2*p+1][3] += h1 * w2v.w;
            }
        }
    }

    // reduce plog across the warp's 32 tx values
    #pragma unroll
    for (int off = 16; off > 0; off >>= 1)
        #pragma unroll
        for (int i = 0; i < 8; ++i)
            #pragma unroll
            for (int a = 0; a < 4; ++a)
                plog[i][a] += __shfl_xor_sync(0xffffffffu, plog[i][a], off);

    int lane = tid & 31, wrp = tid >> 5;
    if (lane == 0) {
        #pragma unroll
        for (int i = 0; i < 8; ++i)
            #pragma unroll
            for (int a = 0; a < 4; ++a)
                part[wrp*32 + i*4 + a] = plog[i][a];
    }
    __syncthreads();

    if (tid < MT) {                          // one thread per row
        int m   = tid;
        int tyg = m >> 3, mi = m & 7;
        float z[4];
        #pragma unroll
        for (int a = 0; a < 4; ++a)
            z[a] = part[(2*tyg)*32 + mi*4 + a] + part[(2*tyg+1)*32 + mi*4 + a]
                 + b2[a];
        float zm = fmaxf(fmaxf(z[0], z[1]), fmaxf(z[2], z[3]));
        float se = expf(z[0]-zm) + expf(z[1]-zm) + expf(z[2]-zm) + expf(z[3]-zm);
        float lse = zm + logf(se);
        int t = t_base + m;
        float contrib = 0.f;
        if (t < len) {
            int act = actions[b*MAXT + t];
            contrib = z[act] - lse;
        }
        red[m] = contrib;
    }
    __syncthreads();
    if (tid == 0) {
        float s = 0.f;
        #pragma unroll
        for (int m = 0; m < MT; ++m) s += red[m];
        g_blocksums[bid] = s;
    }
}

extern "C" __global__ void traj_reduce(float* __restrict__ out)
{
    __shared__ float sm[NBLK];
    int i = threadIdx.x;
    sm[i] = g_blocksums[i];
    __syncthreads();
    for (int off = NBLK/2; off > 0; off >>= 1) {
        if (i < off) sm[i] += sm[i + off];
        __syncthreads();
    }
    if (i == 0) out[0] = -sm[0];
}

extern "C" void kernel_launch(void* const* d_in, const int* in_sizes, int n_in,
                              void* d_out, int out_size)
{
    const float* s_in    = (const float*)d_in[0];
    const int*   actions = (const int*)  d_in[1];
    const int*   lengths = (const int*)  d_in[2];
    const float* W1      = (const float*)d_in[3];
    const float* b1      = (const float*)d_in[4];
    const float* W2      = (const float*)d_in[5];
    const float* b2      = (const float*)d_in[6];
    float* out = (float*)d_out;

    cudaFuncSetAttribute(traj_main, cudaFuncAttributeMaxDynamicSharedMemorySize,
                         SMEM_BYTES);

    dim3 grid(TILES_PER_B, BB);
    traj_main<<<grid, THREADS, SMEM_BYTES>>>(s_in, actions, lengths,
                                             W1, b1, W2, b2);
    traj_reduce<<<1, NBLK>>>(out);
}

// round 4
// speedup vs baseline: 4.2708x; 4.2708x over previous
#include <cuda_runtime.h>
#include <cuda_bf16.h>
#include <math.h>
#include <stdint.h>

// Problem constants
#define BB    64
#define MAXT  511
#define TP1   512
#define SDIM  1024
#define HDIM  4096

// Tiling
#define MT       64
#define TILES_PER_B 8
#define NITEMS   (BB*TILES_PER_B)     // 512 work items
#define KC       64                   // k per chunk
#define NCHUNK   (SDIM/KC)            // 16
#define NT       256                  // H cols per n-tile
#define NNT      (HDIM/NT)            // 16
#define THREADS  256
#define GRID     296                  // persistent CTAs (2/SM)

// SMEM layout (bytes)
#define A_OFF(b)  ((b)*8192)              // 2 x 8 KB   (64 rows x 128B)
#define B_OFF(b)  (16384 + (b)*32768)     // 2 x 32 KB  (256 rows x 128B)
#define LOG_OFF   81920                   // 64*4 floats
#define RED_OFF   82944                   // 8 floats
#define ITEM_OFF  82976
#define SMEM_BYTES 83072

#define SW128(x) ((x) ^ (((x) >> 3) & 0x70))

__device__ __nv_bfloat16 g_sbf[(size_t)BB * TP1 * SDIM];   // 67 MB scratch: s in bf16
__device__ __nv_bfloat16 g_w1t[(size_t)HDIM * SDIM];       // 8 MB  scratch: W1^T bf16
__device__ float    g_blocksums[GRID];
__device__ unsigned g_counter;

// ---------------- helpers ----------------
__device__ __forceinline__ uint32_t smem_u32(const void* p) {
    uint32_t a;
    asm("{ .reg .u64 t; cvta.to.shared.u64 t, %1; cvt.u32.u64 %0, t; }" : "=r"(a) : "l"(p));
    return a;
}
__device__ __forceinline__ uint32_t bf2(float x, float y) {
    __nv_bfloat162 h = __float22bfloat162_rn(make_float2(x, y));
    return *(uint32_t*)&h;
}
__device__ __forceinline__ void cp16(uint32_t dst, const void* src) {
    asm volatile("cp.async.cg.shared.global [%0], [%1], 16;" :: "r"(dst), "l"(src));
}
__device__ __forceinline__ void ldsm_x4(uint32_t* r, uint32_t addr) {
    asm volatile("ldmatrix.sync.aligned.m8n8.x4.shared.b16 {%0,%1,%2,%3}, [%4];"
                 : "=r"(r[0]), "=r"(r[1]), "=r"(r[2]), "=r"(r[3]) : "r"(addr));
}
__device__ __forceinline__ void ldsm_x2(uint32_t* r, uint32_t addr) {
    asm volatile("ldmatrix.sync.aligned.m8n8.x2.shared.b16 {%0,%1}, [%2];"
                 : "=r"(r[0]), "=r"(r[1]) : "r"(addr));
}
__device__ __forceinline__ void mma16816(float* d, const uint32_t* a, const uint32_t* b) {
    asm volatile("mma.sync.aligned.m16n8k16.row.col.f32.bf16.bf16.f32 "
                 "{%0,%1,%2,%3}, {%4,%5,%6,%7}, {%8,%9}, {%0,%1,%2,%3};"
                 : "+f"(d[0]), "+f"(d[1]), "+f"(d[2]), "+f"(d[3])
                 : "r"(a[0]), "r"(a[1]), "r"(a[2]), "r"(a[3]), "r"(b[0]), "r"(b[1]));
}

// ---------------- prepass kernels ----------------
extern "C" __global__ void init_counter() { g_counter = 0u; }

// s fp32 -> bf16 (contiguous, 8 elems/thread)
extern "C" __global__ void s_cvt(const float* __restrict__ s) {
    size_t i = (size_t)blockIdx.x * 256 + threadIdx.x;
    const float4* p = (const float4*)s + i * 2;
    float4 v0 = p[0], v1 = p[1];
    uint4 o;
    o.x = bf2(v0.x, v0.y); o.y = bf2(v0.z, v0.w);
    o.z = bf2(v1.x, v1.y); o.w = bf2(v1.z, v1.w);
    ((uint4*)g_sbf)[i] = o;
}

// W1 [S,H] fp32 -> W1T [H,S] bf16
extern "C" __global__ void w1_transpose(const float* __restrict__ W1) {
    __shared__ float tile[32][33];
    int n0 = blockIdx.x * 32, k0 = blockIdx.y * 32;
    int tx = threadIdx.x, ty = threadIdx.y;
    #pragma unroll
    for (int i = 0; i < 32; i += 8)
        tile[ty + i][tx] = W1[(size_t)(k0 + ty + i) * HDIM + n0 + tx];
    __syncthreads();
    #pragma unroll
    for (int i = 0; i < 32; i += 8)
        g_w1t[(size_t)(n0 + ty + i) * SDIM + k0 + tx] = __float2bfloat16(tile[tx][ty + i]);
}

// ---------------- main persistent kernel ----------------
extern "C" __global__ void __launch_bounds__(THREADS, 2)
traj_main(const int* __restrict__ actions, const int* __restrict__ lengths,
          const float* __restrict__ b1, const float* __restrict__ W2,
          const float* __restrict__ b2)
{
    extern __shared__ __align__(1024) char smem[];
    float*    logitsS = (float*)(smem + LOG_OFF);
    float*    redS    = (float*)(smem + RED_OFF);
    unsigned* itemS   = (unsigned*)(smem + ITEM_OFF);
    const uint32_t smem_u = smem_u32(smem);

    const int tid  = threadIdx.x;
    const int lane = tid & 31;
    const int wid  = tid >> 5;
    const int warp_m = wid & 1;         // 2 row-groups of 32
    const int warp_n = wid >> 1;        // 4 col-groups of 64
    const int m0  = warp_m * 32;
    const int n0w = warp_n * 64;

    float total = 0.f;

    for (;;) {
        if (tid == 0) itemS[0] = atomicAdd(&g_counter, 1u);
        __syncthreads();
        const unsigned item = itemS[0];
        __syncthreads();
        if (item >= NITEMS) break;
        const int b = item >> 3, tile = item & 7;
        const int t_base = tile * MT;
        const int len = lengths[b];
        if (t_base >= len) continue;

        logitsS[tid] = 0.f;     // 64 rows x 4 actions

        const __nv_bfloat16* abase = g_sbf + ((size_t)b * TP1 + t_base) * SDIM;

        float plog[4][4];
        #pragma unroll
        for (int i = 0; i < 4; ++i)
            #pragma unroll
            for (int a = 0; a < 4; ++a) plog[i][a] = 0.f;

        for (int nt = 0; nt < NNT; ++nt) {
            const __nv_bfloat16* bbase = g_w1t + (size_t)nt * NT * SDIM;

            float d[2][8][4];
            #pragma unroll
            for (int mi = 0; mi < 2; ++mi)
                #pragma unroll
                for (int ni = 0; ni < 8; ++ni)
                    #pragma unroll
                    for (int k = 0; k < 4; ++k) d[mi][ni][k] = 0.f;

            // ---- preload chunk 0 ----
            {
                #pragma unroll
                for (int i = 0; i < 2; ++i) {
                    int u = tid + i * 256, row = u >> 3, kg = u & 7;
                    cp16(smem_u + A_OFF(0) + SW128(row * 128 + kg * 16),
                         abase + (size_t)row * SDIM + kg * 8);
                }
                #pragma unroll
                for (int i = 0; i < 8; ++i) {
                    int u = tid + i * 256, row = u >> 3, kg = u & 7;
                    cp16(smem_u + B_OFF(0) + SW128(row * 128 + kg * 16),
                         bbase + (size_t)row * SDIM + kg * 8);
                }
                asm volatile("cp.async.commit_group;");
            }

            for (int c = 0; c < NCHUNK; ++c) {
                if (c + 1 < NCHUNK) {
                    const int nb = (c + 1) & 1, koff = (c + 1) * KC;
                    #pragma unroll
                    for (int i = 0; i < 2; ++i) {
                        int u = tid + i * 256, row = u >> 3, kg = u & 7;
                        cp16(smem_u + A_OFF(nb) + SW128(row * 128 + kg * 16),
                             abase + (size_t)row * SDIM + koff + kg * 8);
                    }
                    #pragma unroll
                    for (int i = 0; i < 8; ++i) {
                        int u = tid + i * 256, row = u >> 3, kg = u & 7;
                        cp16(smem_u + B_OFF(nb) + SW128(row * 128 + kg * 16),
                             bbase + (size_t)row * SDIM + koff + kg * 8);
                    }
                    asm volatile("cp.async.commit_group;");
                    asm volatile("cp.async.wait_group 1;");
                } else {
                    asm volatile("cp.async.wait_group 0;");
                }
                __syncthreads();

                const uint32_t aS = smem_u + A_OFF(c & 1);
                const uint32_t bS = smem_u + B_OFF(c & 1);
                #pragma unroll
                for (int ks = 0; ks < 4; ++ks) {
                    uint32_t afr[2][4];
                    #pragma unroll
                    for (int mi = 0; mi < 2; ++mi) {
                        int off = (m0 + mi * 16 + (lane & 15)) * 128
                                + ks * 32 + (lane >> 4) * 16;
                        ldsm_x4(afr[mi], aS + SW128(off));
                    }
                    #pragma unroll
                    for (int ni = 0; ni < 8; ++ni) {
                        uint32_t bfr[2];
                        int off = (n0w + ni * 8 + (lane & 7)) * 128
                                + ks * 32 + ((lane >> 3) & 1) * 16;
                        ldsm_x2(bfr, bS + SW128(off));
                        mma16816(d[0][ni], afr[0], bfr);
                        mma16816(d[1][ni], afr[1], bfr);
                    }
                }
                __syncthreads();
            }

            // ---- fused epilogue: relu(acc+b1) . W2[:,0:4] into plog regs ----
            #pragma unroll
            for (int ni = 0; ni < 8; ++ni) {
                #pragma unroll
                for (int jc = 0; jc < 2; ++jc) {
                    int col = nt * NT + n0w + ni * 8 + 2 * (lane & 3) + jc;
                    float bias = __ldg(b1 + col);
                    float4 w2v = *(const float4*)(W2 + (size_t)col * 32);
                    #pragma unroll
                    for (int mi = 0; mi < 2; ++mi) {
                        #pragma unroll
                        for (int half = 0; half < 2; ++half) {
                            float h = d[mi][ni][half * 2 + jc] + bias;
                            h = fmaxf(h, 0.f);
                            int slot = mi * 2 + half;
                            plog[slot][0] += h * w2v.x;
                            plog[slot][1] += h * w2v.y;
                            plog[slot][2] += h * w2v.z;
                            plog[slot][3] += h * w2v.w;
                        }
                    }
                }
            }
        }

        // ---- flush per-lane partials into shared logits ----
        #pragma unroll
        for (int slot = 0; slot < 4; ++slot) {
            int row = m0 + (slot >> 1) * 16 + (slot & 1) * 8 + (lane >> 2);
            #pragma unroll
            for (int a = 0; a < 4; ++a)
                atomicAdd(&logitsS[row * 4 + a], plog[slot][a]);
        }
        __syncthreads();

        // ---- per-row log-softmax + gather + mask ----
        float contrib = 0.f;
        if (tid < MT) {
            int t = t_base + tid;
            if (t < len) {
                float z[4];
                #pragma unroll
                for (int a = 0; a < 4; ++a)
                    z[a] = logitsS[tid * 4 + a] + __ldg(b2 + a);
                float zm = fmaxf(fmaxf(z[0], z[1]), fmaxf(z[2], z[3]));
                float se = expf(z[0]-zm) + expf(z[1]-zm) + expf(z[2]-zm) + expf(z[3]-zm);
                float lse = zm + logf(se);
                int act = actions[b * MAXT + t];
                contrib = z[act] - lse;
            }
        }
        #pragma unroll
        for (int off = 16; off > 0; off >>= 1)
            contrib += __shfl_xor_sync(0xffffffffu, contrib, off);
        if (lane == 0) redS[wid] = contrib;
        __syncthreads();
        if (tid == 0) {
            float s = 0.f;
            #pragma unroll
            for (int w = 0; w < 8; ++w) s += redS[w];
            total += s;
        }
        __syncthreads();
    }

    if (tid == 0) g_blocksums[blockIdx.x] = total;
}

extern "C" __global__ void traj_reduce(float* __restrict__ out)
{
    __shared__ float sm[512];
    int i = threadIdx.x;
    sm[i] = (i < GRID) ? g_blocksums[i] : 0.f;
    __syncthreads();
    for (int off = 256; off > 0; off >>= 1) {
        if (i < off) sm[i] += sm[i + off];
        __syncthreads();
    }
    if (i == 0) out[0] = -sm[0];
}

extern "C" void kernel_launch(void* const* d_in, const int* in_sizes, int n_in,
                              void* d_out, int out_size)
{
    const float* s_in    = (const float*)d_in[0];
    const int*   actions = (const int*)  d_in[1];
    const int*   lengths = (const int*)  d_in[2];
    const float* W1      = (const float*)d_in[3];
    const float* b1      = (const float*)d_in[4];
    const float* W2      = (const float*)d_in[5];
    const float* b2      = (const float*)d_in[6];
    float* out = (float*)d_out;

    cudaFuncSetAttribute(traj_main, cudaFuncAttributeMaxDynamicSharedMemorySize, SMEM_BYTES);

    init_counter<<<1, 1>>>();
    s_cvt<<<(BB * TP1 * SDIM / 8) / 256, 256>>>(s_in);
    w1_transpose<<<dim3(HDIM / 32, SDIM / 32), dim3(32, 8)>>>(W1);
    traj_main<<<GRID, THREADS, SMEM_BYTES>>>(actions, lengths, b1, W2, b2);
    traj_reduce<<<1, 512>>>(out);
}